// round 1
// baseline (speedup 1.0000x reference)
#include <cuda_runtime.h>

#define BB 2
#define NN 2048
#define CC 1024
#define HH 16
#define DD 64
#define NKC 16   // NN / 128 key chunks

// scratch (device globals: allocation-free)
__device__ float g_q[(size_t)BB*HH*NN*DD];
__device__ float g_k[(size_t)BB*HH*NN*DD];
__device__ float g_v[(size_t)BB*HH*NN*DD];
__device__ float g_a[(size_t)BB*NN*CC];

// ---------------------------------------------------------------------------
// QKV projection: q/k/v = x @ W{q,k,v}, scatter-store to [B,H,N,D]
// 128x128 tile, kt=16, 256 threads, 8x8 per thread
// ---------------------------------------------------------------------------
__global__ void __launch_bounds__(256) qkv_kernel(
    const float* __restrict__ x,
    const float* __restrict__ Wq,
    const float* __restrict__ Wk,
    const float* __restrict__ Wv)
{
    __shared__ float As[16][132];
    __shared__ float Bs[16][128];

    const float* W;
    float* dst;
    if (blockIdx.z == 0)      { W = Wq; dst = g_q; }
    else if (blockIdx.z == 1) { W = Wk; dst = g_k; }
    else                      { W = Wv; dst = g_v; }

    const int tid = threadIdx.x;
    const int tx = tid & 15, ty = tid >> 4;
    const int m0 = blockIdx.x * 128, n0 = blockIdx.y * 128;

    float acc[8][8] = {};

    for (int k0 = 0; k0 < CC; k0 += 16) {
        #pragma unroll
        for (int i = 0; i < 2; i++) {            // A tile 128x16 (transposed into smem)
            int l4 = tid + i * 256;
            int r = l4 >> 2, c4 = (l4 & 3) << 2;
            float4 v = *(const float4*)&x[(size_t)(m0 + r) * CC + k0 + c4];
            As[c4 + 0][r] = v.x; As[c4 + 1][r] = v.y;
            As[c4 + 2][r] = v.z; As[c4 + 3][r] = v.w;
        }
        #pragma unroll
        for (int i = 0; i < 2; i++) {            // B tile 16x128
            int l4 = tid + i * 256;
            int r = l4 >> 5, c4 = (l4 & 31) << 2;
            *(float4*)&Bs[r][c4] = *(const float4*)&W[(size_t)(k0 + r) * CC + n0 + c4];
        }
        __syncthreads();
        #pragma unroll
        for (int kk = 0; kk < 16; kk++) {
            float a[8], b[8];
            *(float4*)&a[0] = *(float4*)&As[kk][ty * 8];
            *(float4*)&a[4] = *(float4*)&As[kk][ty * 8 + 4];
            *(float4*)&b[0] = *(float4*)&Bs[kk][tx * 8];
            *(float4*)&b[4] = *(float4*)&Bs[kk][tx * 8 + 4];
            #pragma unroll
            for (int r = 0; r < 8; r++)
                #pragma unroll
                for (int c = 0; c < 8; c++)
                    acc[r][c] = fmaf(a[r], b[c], acc[r][c]);
        }
        __syncthreads();
    }

    // scatter store to [B,H,N,D]; 8 consecutive cols stay inside one head (n0,tx*8 mult of 8, D=64)
    const int j = n0 + tx * 8;
    const int h = j >> 6, d0 = j & 63;
    #pragma unroll
    for (int r = 0; r < 8; r++) {
        int m = m0 + ty * 8 + r;
        int b = m >> 11, n = m & 2047;
        float* p = &dst[((((size_t)b * HH + h) * NN + n) << 6) + d0];
        *(float4*)p       = make_float4(acc[r][0], acc[r][1], acc[r][2], acc[r][3]);
        *(float4*)(p + 4) = make_float4(acc[r][4], acc[r][5], acc[r][6], acc[r][7]);
    }
}

// ---------------------------------------------------------------------------
// Attention: one block per (b, h, 128-query tile). Per key chunk of 128:
//   S = (Q*scale) @ K^T  (8x8 frag/thread), row softmax (16-lane shfl),
//   P -> smem, O += P @ V with lane*4-row / warp*8-col mapping.
// ---------------------------------------------------------------------------
__global__ void __launch_bounds__(256) attn_kernel()
{
    extern __shared__ float sm[];
    float* qst = sm;                    // [64][132]  q transposed (d-major), pre-scaled
    float* kst = qst + 64 * 132;        // [64][132]  k transposed
    float* vs  = kst + 64 * 132;        // [128][68]  v row-major
    float* pst = vs + 128 * 68;         // [128][132] p transposed: pst[j][i]

    const int tid  = threadIdx.x;
    const int tx   = tid & 15, ty = tid >> 4;   // s-phase mapping
    const int lane = tid & 31, warp = tid >> 5; // pv-phase mapping
    const int qt = blockIdx.x;
    const int h  = blockIdx.y;
    const int b  = blockIdx.z;

    const size_t bh = (size_t)(b * HH + h) * NN * DD;
    const float* qg = g_q + bh + (size_t)qt * 128 * DD;
    const float* kg = g_k + bh;
    const float* vg = g_v + bh;
    const float scale = 0.125f;  // D^-0.5

    // load Q tile transposed (with scale folded in)
    #pragma unroll
    for (int i = 0; i < 8; i++) {
        int l4 = tid + i * 256;          // 2048 float4 total
        int r = l4 >> 4, c4 = (l4 & 15) << 2;
        float4 v = *(const float4*)&qg[r * 64 + c4];
        qst[(c4 + 0) * 132 + r] = v.x * scale;
        qst[(c4 + 1) * 132 + r] = v.y * scale;
        qst[(c4 + 2) * 132 + r] = v.z * scale;
        qst[(c4 + 3) * 132 + r] = v.w * scale;
    }

    float out[4][8] = {};
    const int orow = lane * 4;   // output rows orow..orow+3
    const int ocol = warp * 8;   // output cols ocol..ocol+7

    for (int kc = 0; kc < NKC; kc++) {
        const float* kgc = kg + (size_t)kc * 128 * 64;
        const float* vgc = vg + (size_t)kc * 128 * 64;
        #pragma unroll
        for (int i = 0; i < 8; i++) {
            int l4 = tid + i * 256;
            int r = l4 >> 4, c4 = (l4 & 15) << 2;
            float4 v = *(const float4*)&kgc[r * 64 + c4];
            kst[(c4 + 0) * 132 + r] = v.x;
            kst[(c4 + 1) * 132 + r] = v.y;
            kst[(c4 + 2) * 132 + r] = v.z;
            kst[(c4 + 3) * 132 + r] = v.w;
            *(float4*)&vs[r * 68 + c4] = *(const float4*)&vgc[r * 64 + c4];
        }
        __syncthreads();   // (also covers first-iteration qst visibility)

        // S = Q K^T : rows ty*8.., cols tx*8..
        float s[8][8] = {};
        #pragma unroll 4
        for (int d = 0; d < 64; d++) {
            float a[8], bb[8];
            *(float4*)&a[0]  = *(float4*)&qst[d * 132 + ty * 8];
            *(float4*)&a[4]  = *(float4*)&qst[d * 132 + ty * 8 + 4];
            *(float4*)&bb[0] = *(float4*)&kst[d * 132 + tx * 8];
            *(float4*)&bb[4] = *(float4*)&kst[d * 132 + tx * 8 + 4];
            #pragma unroll
            for (int r = 0; r < 8; r++)
                #pragma unroll
                for (int c = 0; c < 8; c++)
                    s[r][c] = fmaf(a[r], bb[c], s[r][c]);
        }

        // per-row softmax over the 128-wide chunk (row = 16 tx-threads x 8 cols)
        #pragma unroll
        for (int r = 0; r < 8; r++) {
            float mx = s[r][0];
            #pragma unroll
            for (int c = 1; c < 8; c++) mx = fmaxf(mx, s[r][c]);
            #pragma unroll
            for (int off = 8; off; off >>= 1)
                mx = fmaxf(mx, __shfl_xor_sync(0xffffffffu, mx, off));
            float sum = 0.f;
            #pragma unroll
            for (int c = 0; c < 8; c++) { s[r][c] = __expf(s[r][c] - mx); sum += s[r][c]; }
            #pragma unroll
            for (int off = 8; off; off >>= 1)
                sum += __shfl_xor_sync(0xffffffffu, sum, off);
            float inv = 1.0f / sum;
            #pragma unroll
            for (int c = 0; c < 8; c++) s[r][c] *= inv;
        }

        // write P transposed: pst[j][i]
        #pragma unroll
        for (int c = 0; c < 8; c++) {
            int j = tx * 8 + c;
            #pragma unroll
            for (int r = 0; r < 8; r++)
                pst[j * 132 + ty * 8 + r] = s[r][c];
        }
        __syncthreads();

        // O += P @ V
        #pragma unroll 2
        for (int j = 0; j < 128; j++) {
            float4 p4 = *(float4*)&pst[j * 132 + orow];
            float pv[4] = { p4.x, p4.y, p4.z, p4.w };
            float vv[8];
            *(float4*)&vv[0] = *(float4*)&vs[j * 68 + ocol];
            *(float4*)&vv[4] = *(float4*)&vs[j * 68 + ocol + 4];
            #pragma unroll
            for (int r = 0; r < 4; r++)
                #pragma unroll
                for (int e = 0; e < 8; e++)
                    out[r][e] = fmaf(pv[r], vv[e], out[r][e]);
        }
        __syncthreads();  // protect kst/vs/pst before next chunk overwrites
    }

    // store to g_a in [B,N,C] layout: col = h*64 + ocol + e
    #pragma unroll
    for (int r = 0; r < 4; r++) {
        int n = qt * 128 + orow + r;
        float* p = &g_a[((size_t)b * NN + n) * CC + h * 64 + ocol];
        *(float4*)p       = make_float4(out[r][0], out[r][1], out[r][2], out[r][3]);
        *(float4*)(p + 4) = make_float4(out[r][4], out[r][5], out[r][6], out[r][7]);
    }
}

// ---------------------------------------------------------------------------
// Output projection: out = g_a @ Wp + bp
// ---------------------------------------------------------------------------
__global__ void __launch_bounds__(256) proj_kernel(
    const float* __restrict__ Wp,
    const float* __restrict__ bp,
    float* __restrict__ outp)
{
    __shared__ float As[16][132];
    __shared__ float Bs[16][128];

    const int tid = threadIdx.x;
    const int tx = tid & 15, ty = tid >> 4;
    const int m0 = blockIdx.x * 128, n0 = blockIdx.y * 128;

    float acc[8][8] = {};

    for (int k0 = 0; k0 < CC; k0 += 16) {
        #pragma unroll
        for (int i = 0; i < 2; i++) {
            int l4 = tid + i * 256;
            int r = l4 >> 2, c4 = (l4 & 3) << 2;
            float4 v = *(const float4*)&g_a[(size_t)(m0 + r) * CC + k0 + c4];
            As[c4 + 0][r] = v.x; As[c4 + 1][r] = v.y;
            As[c4 + 2][r] = v.z; As[c4 + 3][r] = v.w;
        }
        #pragma unroll
        for (int i = 0; i < 2; i++) {
            int l4 = tid + i * 256;
            int r = l4 >> 5, c4 = (l4 & 31) << 2;
            *(float4*)&Bs[r][c4] = *(const float4*)&Wp[(size_t)(k0 + r) * CC + n0 + c4];
        }
        __syncthreads();
        #pragma unroll
        for (int kk = 0; kk < 16; kk++) {
            float a[8], b[8];
            *(float4*)&a[0] = *(float4*)&As[kk][ty * 8];
            *(float4*)&a[4] = *(float4*)&As[kk][ty * 8 + 4];
            *(float4*)&b[0] = *(float4*)&Bs[kk][tx * 8];
            *(float4*)&b[4] = *(float4*)&Bs[kk][tx * 8 + 4];
            #pragma unroll
            for (int r = 0; r < 8; r++)
                #pragma unroll
                for (int c = 0; c < 8; c++)
                    acc[r][c] = fmaf(a[r], b[c], acc[r][c]);
        }
        __syncthreads();
    }

    float bias[8];
    *(float4*)&bias[0] = *(const float4*)&bp[n0 + tx * 8];
    *(float4*)&bias[4] = *(const float4*)&bp[n0 + tx * 8 + 4];

    #pragma unroll
    for (int r = 0; r < 8; r++) {
        int m = m0 + ty * 8 + r;
        float* p = &outp[(size_t)m * CC + n0 + tx * 8];
        *(float4*)p       = make_float4(acc[r][0] + bias[0], acc[r][1] + bias[1],
                                        acc[r][2] + bias[2], acc[r][3] + bias[3]);
        *(float4*)(p + 4) = make_float4(acc[r][4] + bias[4], acc[r][5] + bias[5],
                                        acc[r][6] + bias[6], acc[r][7] + bias[7]);
    }
}

// ---------------------------------------------------------------------------
extern "C" void kernel_launch(void* const* d_in, const int* in_sizes, int n_in,
                              void* d_out, int out_size)
{
    const float* x  = (const float*)d_in[0];
    const float* Wq = (const float*)d_in[1];
    const float* Wk = (const float*)d_in[2];
    const float* Wv = (const float*)d_in[3];
    const float* Wp = (const float*)d_in[4];
    const float* bp = (const float*)d_in[5];
    float* out = (float*)d_out;

    const int attn_smem = (64*132 + 64*132 + 128*68 + 128*132) * 4;  // 169984 B
    cudaFuncSetAttribute(attn_kernel, cudaFuncAttributeMaxDynamicSharedMemorySize, attn_smem);

    qkv_kernel<<<dim3(32, 8, 3), 256>>>(x, Wq, Wk, Wv);
    attn_kernel<<<dim3(16, 16, 2), 256, attn_smem>>>();
    proj_kernel<<<dim3(32, 8), 256>>>(Wp, bp, out);
}

// round 2
// speedup vs baseline: 1.0002x; 1.0002x over previous
#include <cuda_runtime.h>

#define BB 2
#define NN 2048
#define CC 1024
#define HH 16
#define DD 64
#define NKC 16   // NN / 128 key chunks

// scratch (device globals: allocation-free)
__device__ float g_q[(size_t)BB*HH*NN*DD];
__device__ float g_k[(size_t)BB*HH*NN*DD];
__device__ float g_v[(size_t)BB*HH*NN*DD];
__device__ float g_a[(size_t)BB*NN*CC];

// ---------------------------------------------------------------------------
// QKV projection: q/k/v = x @ W{q,k,v}, scatter-store to [B,H,N,D]
// 128x128 tile, kt=16, 256 threads, 8x8 per thread
// ---------------------------------------------------------------------------
__global__ void __launch_bounds__(256) qkv_kernel(
    const float* __restrict__ x,
    const float* __restrict__ Wq,
    const float* __restrict__ Wk,
    const float* __restrict__ Wv)
{
    __shared__ float As[16][132];
    __shared__ float Bs[16][128];

    const float* W;
    float* dst;
    if (blockIdx.z == 0)      { W = Wq; dst = g_q; }
    else if (blockIdx.z == 1) { W = Wk; dst = g_k; }
    else                      { W = Wv; dst = g_v; }

    const int tid = threadIdx.x;
    const int tx = tid & 15, ty = tid >> 4;
    const int m0 = blockIdx.x * 128, n0 = blockIdx.y * 128;

    float acc[8][8] = {};

    for (int k0 = 0; k0 < CC; k0 += 16) {
        #pragma unroll
        for (int i = 0; i < 2; i++) {            // A tile 128x16 (transposed into smem)
            int l4 = tid + i * 256;
            int r = l4 >> 2, c4 = (l4 & 3) << 2;
            float4 v = *(const float4*)&x[(size_t)(m0 + r) * CC + k0 + c4];
            As[c4 + 0][r] = v.x; As[c4 + 1][r] = v.y;
            As[c4 + 2][r] = v.z; As[c4 + 3][r] = v.w;
        }
        #pragma unroll
        for (int i = 0; i < 2; i++) {            // B tile 16x128
            int l4 = tid + i * 256;
            int r = l4 >> 5, c4 = (l4 & 31) << 2;
            *(float4*)&Bs[r][c4] = *(const float4*)&W[(size_t)(k0 + r) * CC + n0 + c4];
        }
        __syncthreads();
        #pragma unroll
        for (int kk = 0; kk < 16; kk++) {
            float a[8], b[8];
            *(float4*)&a[0] = *(float4*)&As[kk][ty * 8];
            *(float4*)&a[4] = *(float4*)&As[kk][ty * 8 + 4];
            *(float4*)&b[0] = *(float4*)&Bs[kk][tx * 8];
            *(float4*)&b[4] = *(float4*)&Bs[kk][tx * 8 + 4];
            #pragma unroll
            for (int r = 0; r < 8; r++)
                #pragma unroll
                for (int c = 0; c < 8; c++)
                    acc[r][c] = fmaf(a[r], b[c], acc[r][c]);
        }
        __syncthreads();
    }

    // scatter store to [B,H,N,D]; 8 consecutive cols stay inside one head (n0,tx*8 mult of 8, D=64)
    const int j = n0 + tx * 8;
    const int h = j >> 6, d0 = j & 63;
    #pragma unroll
    for (int r = 0; r < 8; r++) {
        int m = m0 + ty * 8 + r;
        int b = m >> 11, n = m & 2047;
        float* p = &dst[((((size_t)b * HH + h) * NN + n) << 6) + d0];
        *(float4*)p       = make_float4(acc[r][0], acc[r][1], acc[r][2], acc[r][3]);
        *(float4*)(p + 4) = make_float4(acc[r][4], acc[r][5], acc[r][6], acc[r][7]);
    }
}

// ---------------------------------------------------------------------------
// Attention: one block per (b, h, 128-query tile). Per key chunk of 128:
//   S = (Q*scale) @ K^T  (8x8 frag/thread), row softmax (16-lane shfl),
//   P -> smem, O += P @ V with lane*4-row / warp*8-col mapping.
// ---------------------------------------------------------------------------
__global__ void __launch_bounds__(256) attn_kernel()
{
    extern __shared__ float sm[];
    float* qst = sm;                    // [64][132]  q transposed (d-major), pre-scaled
    float* kst = qst + 64 * 132;        // [64][132]  k transposed
    float* vs  = kst + 64 * 132;        // [128][68]  v row-major
    float* pst = vs + 128 * 68;         // [128][132] p transposed: pst[j][i]

    const int tid  = threadIdx.x;
    const int tx   = tid & 15, ty = tid >> 4;   // s-phase mapping
    const int lane = tid & 31, warp = tid >> 5; // pv-phase mapping
    const int qt = blockIdx.x;
    const int h  = blockIdx.y;
    const int b  = blockIdx.z;

    const size_t bh = (size_t)(b * HH + h) * NN * DD;
    const float* qg = g_q + bh + (size_t)qt * 128 * DD;
    const float* kg = g_k + bh;
    const float* vg = g_v + bh;
    const float scale = 0.125f;  // D^-0.5

    // load Q tile transposed (with scale folded in)
    #pragma unroll
    for (int i = 0; i < 8; i++) {
        int l4 = tid + i * 256;          // 2048 float4 total
        int r = l4 >> 4, c4 = (l4 & 15) << 2;
        float4 v = *(const float4*)&qg[r * 64 + c4];
        qst[(c4 + 0) * 132 + r] = v.x * scale;
        qst[(c4 + 1) * 132 + r] = v.y * scale;
        qst[(c4 + 2) * 132 + r] = v.z * scale;
        qst[(c4 + 3) * 132 + r] = v.w * scale;
    }

    float out[4][8] = {};
    const int orow = lane * 4;   // output rows orow..orow+3
    const int ocol = warp * 8;   // output cols ocol..ocol+7

    for (int kc = 0; kc < NKC; kc++) {
        const float* kgc = kg + (size_t)kc * 128 * 64;
        const float* vgc = vg + (size_t)kc * 128 * 64;
        #pragma unroll
        for (int i = 0; i < 8; i++) {
            int l4 = tid + i * 256;
            int r = l4 >> 4, c4 = (l4 & 15) << 2;
            float4 v = *(const float4*)&kgc[r * 64 + c4];
            kst[(c4 + 0) * 132 + r] = v.x;
            kst[(c4 + 1) * 132 + r] = v.y;
            kst[(c4 + 2) * 132 + r] = v.z;
            kst[(c4 + 3) * 132 + r] = v.w;
            *(float4*)&vs[r * 68 + c4] = *(const float4*)&vgc[r * 64 + c4];
        }
        __syncthreads();   // (also covers first-iteration qst visibility)

        // S = Q K^T : rows ty*8.., cols tx*8..
        float s[8][8] = {};
        #pragma unroll 4
        for (int d = 0; d < 64; d++) {
            float a[8], bb[8];
            *(float4*)&a[0]  = *(float4*)&qst[d * 132 + ty * 8];
            *(float4*)&a[4]  = *(float4*)&qst[d * 132 + ty * 8 + 4];
            *(float4*)&bb[0] = *(float4*)&kst[d * 132 + tx * 8];
            *(float4*)&bb[4] = *(float4*)&kst[d * 132 + tx * 8 + 4];
            #pragma unroll
            for (int r = 0; r < 8; r++)
                #pragma unroll
                for (int c = 0; c < 8; c++)
                    s[r][c] = fmaf(a[r], bb[c], s[r][c]);
        }

        // per-row softmax over the 128-wide chunk (row = 16 tx-threads x 8 cols)
        #pragma unroll
        for (int r = 0; r < 8; r++) {
            float mx = s[r][0];
            #pragma unroll
            for (int c = 1; c < 8; c++) mx = fmaxf(mx, s[r][c]);
            #pragma unroll
            for (int off = 8; off; off >>= 1)
                mx = fmaxf(mx, __shfl_xor_sync(0xffffffffu, mx, off));
            float sum = 0.f;
            #pragma unroll
            for (int c = 0; c < 8; c++) { s[r][c] = __expf(s[r][c] - mx); sum += s[r][c]; }
            #pragma unroll
            for (int off = 8; off; off >>= 1)
                sum += __shfl_xor_sync(0xffffffffu, sum, off);
            float inv = 1.0f / sum;
            #pragma unroll
            for (int c = 0; c < 8; c++) s[r][c] *= inv;
        }

        // write P transposed: pst[j][i]
        #pragma unroll
        for (int c = 0; c < 8; c++) {
            int j = tx * 8 + c;
            #pragma unroll
            for (int r = 0; r < 8; r++)
                pst[j * 132 + ty * 8 + r] = s[r][c];
        }
        __syncthreads();

        // O += P @ V
        #pragma unroll 2
        for (int j = 0; j < 128; j++) {
            float4 p4 = *(float4*)&pst[j * 132 + orow];
            float pv[4] = { p4.x, p4.y, p4.z, p4.w };
            float vv[8];
            *(float4*)&vv[0] = *(float4*)&vs[j * 68 + ocol];
            *(float4*)&vv[4] = *(float4*)&vs[j * 68 + ocol + 4];
            #pragma unroll
            for (int r = 0; r < 4; r++)
                #pragma unroll
                for (int e = 0; e < 8; e++)
                    out[r][e] = fmaf(pv[r], vv[e], out[r][e]);
        }
        __syncthreads();  // protect kst/vs/pst before next chunk overwrites
    }

    // store to g_a in [B,N,C] layout: col = h*64 + ocol + e
    #pragma unroll
    for (int r = 0; r < 4; r++) {
        int n = qt * 128 + orow + r;
        float* p = &g_a[((size_t)b * NN + n) * CC + h * 64 + ocol];
        *(float4*)p       = make_float4(out[r][0], out[r][1], out[r][2], out[r][3]);
        *(float4*)(p + 4) = make_float4(out[r][4], out[r][5], out[r][6], out[r][7]);
    }
}

// ---------------------------------------------------------------------------
// Output projection: out = g_a @ Wp + bp
// ---------------------------------------------------------------------------
__global__ void __launch_bounds__(256) proj_kernel(
    const float* __restrict__ Wp,
    const float* __restrict__ bp,
    float* __restrict__ outp)
{
    __shared__ float As[16][132];
    __shared__ float Bs[16][128];

    const int tid = threadIdx.x;
    const int tx = tid & 15, ty = tid >> 4;
    const int m0 = blockIdx.x * 128, n0 = blockIdx.y * 128;

    float acc[8][8] = {};

    for (int k0 = 0; k0 < CC; k0 += 16) {
        #pragma unroll
        for (int i = 0; i < 2; i++) {
            int l4 = tid + i * 256;
            int r = l4 >> 2, c4 = (l4 & 3) << 2;
            float4 v = *(const float4*)&g_a[(size_t)(m0 + r) * CC + k0 + c4];
            As[c4 + 0][r] = v.x; As[c4 + 1][r] = v.y;
            As[c4 + 2][r] = v.z; As[c4 + 3][r] = v.w;
        }
        #pragma unroll
        for (int i = 0; i < 2; i++) {
            int l4 = tid + i * 256;
            int r = l4 >> 5, c4 = (l4 & 31) << 2;
            *(float4*)&Bs[r][c4] = *(const float4*)&Wp[(size_t)(k0 + r) * CC + n0 + c4];
        }
        __syncthreads();
        #pragma unroll
        for (int kk = 0; kk < 16; kk++) {
            float a[8], b[8];
            *(float4*)&a[0] = *(float4*)&As[kk][ty * 8];
            *(float4*)&a[4] = *(float4*)&As[kk][ty * 8 + 4];
            *(float4*)&b[0] = *(float4*)&Bs[kk][tx * 8];
            *(float4*)&b[4] = *(float4*)&Bs[kk][tx * 8 + 4];
            #pragma unroll
            for (int r = 0; r < 8; r++)
                #pragma unroll
                for (int c = 0; c < 8; c++)
                    acc[r][c] = fmaf(a[r], b[c], acc[r][c]);
        }
        __syncthreads();
    }

    float bias[8];
    *(float4*)&bias[0] = *(const float4*)&bp[n0 + tx * 8];
    *(float4*)&bias[4] = *(const float4*)&bp[n0 + tx * 8 + 4];

    #pragma unroll
    for (int r = 0; r < 8; r++) {
        int m = m0 + ty * 8 + r;
        float* p = &outp[(size_t)m * CC + n0 + tx * 8];
        *(float4*)p       = make_float4(acc[r][0] + bias[0], acc[r][1] + bias[1],
                                        acc[r][2] + bias[2], acc[r][3] + bias[3]);
        *(float4*)(p + 4) = make_float4(acc[r][4] + bias[4], acc[r][5] + bias[5],
                                        acc[r][6] + bias[6], acc[r][7] + bias[7]);
    }
}

// ---------------------------------------------------------------------------
extern "C" void kernel_launch(void* const* d_in, const int* in_sizes, int n_in,
                              void* d_out, int out_size)
{
    const float* x  = (const float*)d_in[0];
    const float* Wq = (const float*)d_in[1];
    const float* Wk = (const float*)d_in[2];
    const float* Wv = (const float*)d_in[3];
    const float* Wp = (const float*)d_in[4];
    const float* bp = (const float*)d_in[5];
    float* out = (float*)d_out;

    const int attn_smem = (64*132 + 64*132 + 128*68 + 128*132) * 4;  // 169984 B
    cudaFuncSetAttribute(attn_kernel, cudaFuncAttributeMaxDynamicSharedMemorySize, attn_smem);

    qkv_kernel<<<dim3(32, 8, 3), 256>>>(x, Wq, Wk, Wv);
    attn_kernel<<<dim3(16, 16, 2), 256, attn_smem>>>();
    proj_kernel<<<dim3(32, 8), 256>>>(Wp, bp, out);
}

// round 3
// speedup vs baseline: 1.0004x; 1.0002x over previous
#include <cuda_runtime.h>

#define BB 2
#define NN 2048
#define CC 1024
#define HH 16
#define DD 64
#define NKC 16   // NN / 128 key chunks

// scratch (device globals: allocation-free)
__device__ float g_q[(size_t)BB*HH*NN*DD];
__device__ float g_k[(size_t)BB*HH*NN*DD];
__device__ float g_v[(size_t)BB*HH*NN*DD];
__device__ float g_a[(size_t)BB*NN*CC];

// ---------------------------------------------------------------------------
// QKV projection: q/k/v = x @ W{q,k,v}, scatter-store to [B,H,N,D]
// 128x128 tile, kt=16, 256 threads, 8x8 per thread
// ---------------------------------------------------------------------------
__global__ void __launch_bounds__(256) qkv_kernel(
    const float* __restrict__ x,
    const float* __restrict__ Wq,
    const float* __restrict__ Wk,
    const float* __restrict__ Wv)
{
    __shared__ float As[16][132];
    __shared__ float Bs[16][128];

    const float* W;
    float* dst;
    if (blockIdx.z == 0)      { W = Wq; dst = g_q; }
    else if (blockIdx.z == 1) { W = Wk; dst = g_k; }
    else                      { W = Wv; dst = g_v; }

    const int tid = threadIdx.x;
    const int tx = tid & 15, ty = tid >> 4;
    const int m0 = blockIdx.x * 128, n0 = blockIdx.y * 128;

    float acc[8][8] = {};

    for (int k0 = 0; k0 < CC; k0 += 16) {
        #pragma unroll
        for (int i = 0; i < 2; i++) {            // A tile 128x16 (transposed into smem)
            int l4 = tid + i * 256;
            int r = l4 >> 2, c4 = (l4 & 3) << 2;
            float4 v = *(const float4*)&x[(size_t)(m0 + r) * CC + k0 + c4];
            As[c4 + 0][r] = v.x; As[c4 + 1][r] = v.y;
            As[c4 + 2][r] = v.z; As[c4 + 3][r] = v.w;
        }
        #pragma unroll
        for (int i = 0; i < 2; i++) {            // B tile 16x128
            int l4 = tid + i * 256;
            int r = l4 >> 5, c4 = (l4 & 31) << 2;
            *(float4*)&Bs[r][c4] = *(const float4*)&W[(size_t)(k0 + r) * CC + n0 + c4];
        }
        __syncthreads();
        #pragma unroll
        for (int kk = 0; kk < 16; kk++) {
            float a[8], b[8];
            *(float4*)&a[0] = *(float4*)&As[kk][ty * 8];
            *(float4*)&a[4] = *(float4*)&As[kk][ty * 8 + 4];
            *(float4*)&b[0] = *(float4*)&Bs[kk][tx * 8];
            *(float4*)&b[4] = *(float4*)&Bs[kk][tx * 8 + 4];
            #pragma unroll
            for (int r = 0; r < 8; r++)
                #pragma unroll
                for (int c = 0; c < 8; c++)
                    acc[r][c] = fmaf(a[r], b[c], acc[r][c]);
        }
        __syncthreads();
    }

    // scatter store to [B,H,N,D]; 8 consecutive cols stay inside one head (n0,tx*8 mult of 8, D=64)
    const int j = n0 + tx * 8;
    const int h = j >> 6, d0 = j & 63;
    #pragma unroll
    for (int r = 0; r < 8; r++) {
        int m = m0 + ty * 8 + r;
        int b = m >> 11, n = m & 2047;
        float* p = &dst[((((size_t)b * HH + h) * NN + n) << 6) + d0];
        *(float4*)p       = make_float4(acc[r][0], acc[r][1], acc[r][2], acc[r][3]);
        *(float4*)(p + 4) = make_float4(acc[r][4], acc[r][5], acc[r][6], acc[r][7]);
    }
}

// ---------------------------------------------------------------------------
// Attention: one block per (b, h, 128-query tile). Per key chunk of 128:
//   S = (Q*scale) @ K^T  (8x8 frag/thread), row softmax (16-lane shfl),
//   P -> smem, O += P @ V with lane*4-row / warp*8-col mapping.
// ---------------------------------------------------------------------------
__global__ void __launch_bounds__(256) attn_kernel()
{
    extern __shared__ float sm[];
    float* qst = sm;                    // [64][132]  q transposed (d-major), pre-scaled
    float* kst = qst + 64 * 132;        // [64][132]  k transposed
    float* vs  = kst + 64 * 132;        // [128][68]  v row-major
    float* pst = vs + 128 * 68;         // [128][132] p transposed: pst[j][i]

    const int tid  = threadIdx.x;
    const int tx   = tid & 15, ty = tid >> 4;   // s-phase mapping
    const int lane = tid & 31, warp = tid >> 5; // pv-phase mapping
    const int qt = blockIdx.x;
    const int h  = blockIdx.y;
    const int b  = blockIdx.z;

    const size_t bh = (size_t)(b * HH + h) * NN * DD;
    const float* qg = g_q + bh + (size_t)qt * 128 * DD;
    const float* kg = g_k + bh;
    const float* vg = g_v + bh;
    const float scale = 0.125f;  // D^-0.5

    // load Q tile transposed (with scale folded in)
    #pragma unroll
    for (int i = 0; i < 8; i++) {
        int l4 = tid + i * 256;          // 2048 float4 total
        int r = l4 >> 4, c4 = (l4 & 15) << 2;
        float4 v = *(const float4*)&qg[r * 64 + c4];
        qst[(c4 + 0) * 132 + r] = v.x * scale;
        qst[(c4 + 1) * 132 + r] = v.y * scale;
        qst[(c4 + 2) * 132 + r] = v.z * scale;
        qst[(c4 + 3) * 132 + r] = v.w * scale;
    }

    float out[4][8] = {};
    const int orow = lane * 4;   // output rows orow..orow+3
    const int ocol = warp * 8;   // output cols ocol..ocol+7

    for (int kc = 0; kc < NKC; kc++) {
        const float* kgc = kg + (size_t)kc * 128 * 64;
        const float* vgc = vg + (size_t)kc * 128 * 64;
        #pragma unroll
        for (int i = 0; i < 8; i++) {
            int l4 = tid + i * 256;
            int r = l4 >> 4, c4 = (l4 & 15) << 2;
            float4 v = *(const float4*)&kgc[r * 64 + c4];
            kst[(c4 + 0) * 132 + r] = v.x;
            kst[(c4 + 1) * 132 + r] = v.y;
            kst[(c4 + 2) * 132 + r] = v.z;
            kst[(c4 + 3) * 132 + r] = v.w;
            *(float4*)&vs[r * 68 + c4] = *(const float4*)&vgc[r * 64 + c4];
        }
        __syncthreads();   // (also covers first-iteration qst visibility)

        // S = Q K^T : rows ty*8.., cols tx*8..
        float s[8][8] = {};
        #pragma unroll 4
        for (int d = 0; d < 64; d++) {
            float a[8], bb[8];
            *(float4*)&a[0]  = *(float4*)&qst[d * 132 + ty * 8];
            *(float4*)&a[4]  = *(float4*)&qst[d * 132 + ty * 8 + 4];
            *(float4*)&bb[0] = *(float4*)&kst[d * 132 + tx * 8];
            *(float4*)&bb[4] = *(float4*)&kst[d * 132 + tx * 8 + 4];
            #pragma unroll
            for (int r = 0; r < 8; r++)
                #pragma unroll
                for (int c = 0; c < 8; c++)
                    s[r][c] = fmaf(a[r], bb[c], s[r][c]);
        }

        // per-row softmax over the 128-wide chunk (row = 16 tx-threads x 8 cols)
        #pragma unroll
        for (int r = 0; r < 8; r++) {
            float mx = s[r][0];
            #pragma unroll
            for (int c = 1; c < 8; c++) mx = fmaxf(mx, s[r][c]);
            #pragma unroll
            for (int off = 8; off; off >>= 1)
                mx = fmaxf(mx, __shfl_xor_sync(0xffffffffu, mx, off));
            float sum = 0.f;
            #pragma unroll
            for (int c = 0; c < 8; c++) { s[r][c] = __expf(s[r][c] - mx); sum += s[r][c]; }
            #pragma unroll
            for (int off = 8; off; off >>= 1)
                sum += __shfl_xor_sync(0xffffffffu, sum, off);
            float inv = 1.0f / sum;
            #pragma unroll
            for (int c = 0; c < 8; c++) s[r][c] *= inv;
        }

        // write P transposed: pst[j][i]
        #pragma unroll
        for (int c = 0; c < 8; c++) {
            int j = tx * 8 + c;
            #pragma unroll
            for (int r = 0; r < 8; r++)
                pst[j * 132 + ty * 8 + r] = s[r][c];
        }
        __syncthreads();

        // O += P @ V
        #pragma unroll 2
        for (int j = 0; j < 128; j++) {
            float4 p4 = *(float4*)&pst[j * 132 + orow];
            float pv[4] = { p4.x, p4.y, p4.z, p4.w };
            float vv[8];
            *(float4*)&vv[0] = *(float4*)&vs[j * 68 + ocol];
            *(float4*)&vv[4] = *(float4*)&vs[j * 68 + ocol + 4];
            #pragma unroll
            for (int r = 0; r < 4; r++)
                #pragma unroll
                for (int e = 0; e < 8; e++)
                    out[r][e] = fmaf(pv[r], vv[e], out[r][e]);
        }
        __syncthreads();  // protect kst/vs/pst before next chunk overwrites
    }

    // store to g_a in [B,N,C] layout: col = h*64 + ocol + e
    #pragma unroll
    for (int r = 0; r < 4; r++) {
        int n = qt * 128 + orow + r;
        float* p = &g_a[((size_t)b * NN + n) * CC + h * 64 + ocol];
        *(float4*)p       = make_float4(out[r][0], out[r][1], out[r][2], out[r][3]);
        *(float4*)(p + 4) = make_float4(out[r][4], out[r][5], out[r][6], out[r][7]);
    }
}

// ---------------------------------------------------------------------------
// Output projection: out = g_a @ Wp + bp
// ---------------------------------------------------------------------------
__global__ void __launch_bounds__(256) proj_kernel(
    const float* __restrict__ Wp,
    const float* __restrict__ bp,
    float* __restrict__ outp)
{
    __shared__ float As[16][132];
    __shared__ float Bs[16][128];

    const int tid = threadIdx.x;
    const int tx = tid & 15, ty = tid >> 4;
    const int m0 = blockIdx.x * 128, n0 = blockIdx.y * 128;

    float acc[8][8] = {};

    for (int k0 = 0; k0 < CC; k0 += 16) {
        #pragma unroll
        for (int i = 0; i < 2; i++) {
            int l4 = tid + i * 256;
            int r = l4 >> 2, c4 = (l4 & 3) << 2;
            float4 v = *(const float4*)&g_a[(size_t)(m0 + r) * CC + k0 + c4];
            As[c4 + 0][r] = v.x; As[c4 + 1][r] = v.y;
            As[c4 + 2][r] = v.z; As[c4 + 3][r] = v.w;
        }
        #pragma unroll
        for (int i = 0; i < 2; i++) {
            int l4 = tid + i * 256;
            int r = l4 >> 5, c4 = (l4 & 31) << 2;
            *(float4*)&Bs[r][c4] = *(const float4*)&Wp[(size_t)(k0 + r) * CC + n0 + c4];
        }
        __syncthreads();
        #pragma unroll
        for (int kk = 0; kk < 16; kk++) {
            float a[8], b[8];
            *(float4*)&a[0] = *(float4*)&As[kk][ty * 8];
            *(float4*)&a[4] = *(float4*)&As[kk][ty * 8 + 4];
            *(float4*)&b[0] = *(float4*)&Bs[kk][tx * 8];
            *(float4*)&b[4] = *(float4*)&Bs[kk][tx * 8 + 4];
            #pragma unroll
            for (int r = 0; r < 8; r++)
                #pragma unroll
                for (int c = 0; c < 8; c++)
                    acc[r][c] = fmaf(a[r], b[c], acc[r][c]);
        }
        __syncthreads();
    }

    float bias[8];
    *(float4*)&bias[0] = *(const float4*)&bp[n0 + tx * 8];
    *(float4*)&bias[4] = *(const float4*)&bp[n0 + tx * 8 + 4];

    #pragma unroll
    for (int r = 0; r < 8; r++) {
        int m = m0 + ty * 8 + r;
        float* p = &outp[(size_t)m * CC + n0 + tx * 8];
        *(float4*)p       = make_float4(acc[r][0] + bias[0], acc[r][1] + bias[1],
                                        acc[r][2] + bias[2], acc[r][3] + bias[3]);
        *(float4*)(p + 4) = make_float4(acc[r][4] + bias[4], acc[r][5] + bias[5],
                                        acc[r][6] + bias[6], acc[r][7] + bias[7]);
    }
}

// ---------------------------------------------------------------------------
extern "C" void kernel_launch(void* const* d_in, const int* in_sizes, int n_in,
                              void* d_out, int out_size)
{
    const float* x  = (const float*)d_in[0];
    const float* Wq = (const float*)d_in[1];
    const float* Wk = (const float*)d_in[2];
    const float* Wv = (const float*)d_in[3];
    const float* Wp = (const float*)d_in[4];
    const float* bp = (const float*)d_in[5];
    float* out = (float*)d_out;

    const int attn_smem = (64*132 + 64*132 + 128*68 + 128*132) * 4;  // 169984 B
    cudaFuncSetAttribute(attn_kernel, cudaFuncAttributeMaxDynamicSharedMemorySize, attn_smem);

    qkv_kernel<<<dim3(32, 8, 3), 256>>>(x, Wq, Wk, Wv);
    attn_kernel<<<dim3(16, 16, 2), 256, attn_smem>>>();
    proj_kernel<<<dim3(32, 8), 256>>>(Wp, bp, out);
}

// round 11
// speedup vs baseline: 2.8270x; 2.8258x over previous
#include <cuda_runtime.h>

#define BB 2
#define NN 2048
#define CC 1024
#define HH 16
#define DD 64
#define NKC 16

typedef unsigned int u32;

// scratch (device globals: allocation-free)
__device__ float g_q[(size_t)BB*HH*NN*DD];
__device__ float g_k[(size_t)BB*HH*NN*DD];
__device__ float g_v[(size_t)BB*HH*NN*DD];
__device__ float g_a[(size_t)BB*NN*CC];

__device__ __forceinline__ u32 f2tf(float f) {
    u32 r; asm("cvt.rna.tf32.f32 %0, %1;" : "=r"(r) : "f"(f)); return r;
}

// D += A(16x8) * B(8x8), tf32 inputs, fp32 accum. Standard sm_80 fragment layout.
__device__ __forceinline__ void mma8(float d[4], const u32 a[4], const u32 b[2]) {
    asm volatile(
        "mma.sync.aligned.m16n8k8.row.col.f32.tf32.tf32.f32 "
        "{%0,%1,%2,%3}, {%4,%5,%6,%7}, {%8,%9}, {%0,%1,%2,%3};"
        : "+f"(d[0]), "+f"(d[1]), "+f"(d[2]), "+f"(d[3])
        : "r"(a[0]), "r"(a[1]), "r"(a[2]), "r"(a[3]), "r"(b[0]), "r"(b[1]));
}

// ---------------------------------------------------------------------------
// Tensor-core GEMM core: C[128x128] = A[128xCC] @ W[CCx128] tile
// 8 warps (2m x 4n), warp tile 64x32, k-chunk 32, double-buffered smem.
// Padded strides: A rows 36 words, B rows 132 words -> conflict-free frag LDS.
// ---------------------------------------------------------------------------
#define GA_STR 36
#define GB_STR 132
#define GA_SZ (128 * GA_STR)   // 4608 u32
#define GB_SZ (32 * GB_STR)    // 4224 u32
#define G_SMEM_BYTES ((2 * (GA_SZ + GB_SZ)) * 4)  // 70656

__device__ __forceinline__ void gemm_tc(const float* __restrict__ A,
                                        const float* __restrict__ W,
                                        u32* As, u32* Bs,
                                        float acc[4][4][4],
                                        int m0, int n0, int tid)
{
    const int lane = tid & 31, wid = tid >> 5;
    const int gid = lane >> 2, tidg = lane & 3;
    const int wm = wid >> 2, wn = wid & 3;

    float4 pa[4], pb[4];
    #pragma unroll
    for (int i = 0; i < 4; i++) {                       // prefetch chunk 0
        int idx = tid + i * 256;
        pa[i] = *(const float4*)&A[(size_t)(m0 + (idx >> 3)) * CC + ((idx & 7) << 2)];
        pb[i] = *(const float4*)&W[(size_t)(idx >> 5) * CC + n0 + ((idx & 31) << 2)];
    }
    #pragma unroll
    for (int i = 0; i < 4; i++) {
        int idx = tid + i * 256;
        u32* pA = &As[(idx >> 3) * GA_STR + ((idx & 7) << 2)];
        pA[0] = f2tf(pa[i].x); pA[1] = f2tf(pa[i].y); pA[2] = f2tf(pa[i].z); pA[3] = f2tf(pa[i].w);
        u32* pB = &Bs[(idx >> 5) * GB_STR + ((idx & 31) << 2)];
        pB[0] = f2tf(pb[i].x); pB[1] = f2tf(pb[i].y); pB[2] = f2tf(pb[i].z); pB[3] = f2tf(pb[i].w);
    }
    __syncthreads();

    #pragma unroll 1
    for (int it = 0; it < CC / 32; ++it) {
        const int buf = it & 1;
        const u32* Ab = As + buf * GA_SZ;
        const u32* Bb = Bs + buf * GB_SZ;
        if (it + 1 < CC / 32) {                          // prefetch next chunk
            int k0 = (it + 1) * 32;
            #pragma unroll
            for (int i = 0; i < 4; i++) {
                int idx = tid + i * 256;
                pa[i] = *(const float4*)&A[(size_t)(m0 + (idx >> 3)) * CC + k0 + ((idx & 7) << 2)];
                pb[i] = *(const float4*)&W[(size_t)(k0 + (idx >> 5)) * CC + n0 + ((idx & 31) << 2)];
            }
        }
        #pragma unroll
        for (int ks = 0; ks < 4; ++ks) {
            const int k0 = ks * 8;
            u32 af[4][4], bf[4][2];
            #pragma unroll
            for (int mt = 0; mt < 4; mt++) {
                int r = wm * 64 + mt * 16 + gid;
                af[mt][0] = Ab[r * GA_STR + k0 + tidg];
                af[mt][1] = Ab[(r + 8) * GA_STR + k0 + tidg];
                af[mt][2] = Ab[r * GA_STR + k0 + tidg + 4];
                af[mt][3] = Ab[(r + 8) * GA_STR + k0 + tidg + 4];
            }
            #pragma unroll
            for (int nt = 0; nt < 4; nt++) {
                int c = wn * 32 + nt * 8 + gid;
                bf[nt][0] = Bb[(k0 + tidg) * GB_STR + c];
                bf[nt][1] = Bb[(k0 + tidg + 4) * GB_STR + c];
            }
            #pragma unroll
            for (int mt = 0; mt < 4; mt++)
                #pragma unroll
                for (int nt = 0; nt < 4; nt++)
                    mma8(acc[mt][nt], af[mt], bf[nt]);
        }
        if (it + 1 < CC / 32) {
            u32* An = As + (buf ^ 1) * GA_SZ;
            u32* Bn = Bs + (buf ^ 1) * GB_SZ;
            #pragma unroll
            for (int i = 0; i < 4; i++) {
                int idx = tid + i * 256;
                u32* pA = &An[(idx >> 3) * GA_STR + ((idx & 7) << 2)];
                pA[0] = f2tf(pa[i].x); pA[1] = f2tf(pa[i].y); pA[2] = f2tf(pa[i].z); pA[3] = f2tf(pa[i].w);
                u32* pB = &Bn[(idx >> 5) * GB_STR + ((idx & 31) << 2)];
                pB[0] = f2tf(pb[i].x); pB[1] = f2tf(pb[i].y); pB[2] = f2tf(pb[i].z); pB[3] = f2tf(pb[i].w);
            }
        }
        __syncthreads();
    }
}

// ---------------------------------------------------------------------------
// QKV: q/k/v = x @ W{q,k,v}, scatter to [B,H,N,D]
// ---------------------------------------------------------------------------
__global__ void __launch_bounds__(256) qkv_kernel(
    const float* __restrict__ x, const float* __restrict__ Wq,
    const float* __restrict__ Wk, const float* __restrict__ Wv)
{
    extern __shared__ u32 sm[];
    u32* As = sm;
    u32* Bs = sm + 2 * GA_SZ;

    const float* W; float* dst;
    if (blockIdx.z == 0)      { W = Wq; dst = g_q; }
    else if (blockIdx.z == 1) { W = Wk; dst = g_k; }
    else                      { W = Wv; dst = g_v; }

    const int tid = threadIdx.x;
    const int m0 = blockIdx.x * 128, n0 = blockIdx.y * 128;

    float acc[4][4][4] = {};
    gemm_tc(x, W, As, Bs, acc, m0, n0, tid);

    const int lane = tid & 31, wid = tid >> 5;
    const int gid = lane >> 2, tidg = lane & 3;
    const int wm = wid >> 2, wn = wid & 3;
    #pragma unroll
    for (int mt = 0; mt < 4; mt++)
        #pragma unroll
        for (int h2 = 0; h2 < 2; h2++) {
            int m = m0 + wm * 64 + mt * 16 + h2 * 8 + gid;
            int b = m >> 11, n = m & (NN - 1);
            #pragma unroll
            for (int nt = 0; nt < 4; nt++) {
                int j = n0 + wn * 32 + nt * 8 + tidg * 2;
                int head = j >> 6, d0 = j & 63;
                float2 v = h2 ? make_float2(acc[mt][nt][2], acc[mt][nt][3])
                              : make_float2(acc[mt][nt][0], acc[mt][nt][1]);
                *(float2*)&dst[((((size_t)b * HH + head) * NN + n) << 6) + d0] = v;
            }
        }
}

// ---------------------------------------------------------------------------
// Output projection: out = g_a @ Wp + bp
// ---------------------------------------------------------------------------
__global__ void __launch_bounds__(256) proj_kernel(
    const float* __restrict__ Wp, const float* __restrict__ bp, float* __restrict__ outp)
{
    extern __shared__ u32 sm[];
    u32* As = sm;
    u32* Bs = sm + 2 * GA_SZ;

    const int tid = threadIdx.x;
    const int m0 = blockIdx.x * 128, n0 = blockIdx.y * 128;

    float acc[4][4][4] = {};
    gemm_tc(g_a, Wp, As, Bs, acc, m0, n0, tid);

    const int lane = tid & 31, wid = tid >> 5;
    const int gid = lane >> 2, tidg = lane & 3;
    const int wm = wid >> 2, wn = wid & 3;
    #pragma unroll
    for (int mt = 0; mt < 4; mt++)
        #pragma unroll
        for (int h2 = 0; h2 < 2; h2++) {
            int m = m0 + wm * 64 + mt * 16 + h2 * 8 + gid;
            #pragma unroll
            for (int nt = 0; nt < 4; nt++) {
                int j = n0 + wn * 32 + nt * 8 + tidg * 2;
                float2 bv = *(const float2*)&bp[j];
                float2 v = h2 ? make_float2(acc[mt][nt][2] + bv.x, acc[mt][nt][3] + bv.y)
                              : make_float2(acc[mt][nt][0] + bv.x, acc[mt][nt][1] + bv.y);
                *(float2*)&outp[(size_t)m * CC + j] = v;
            }
        }
}

// ---------------------------------------------------------------------------
// Attention: block per (b,h,128-q tile). S = QK^T and O += PV via mma.sync.
// smem (u32 words): Q[128][68] K[128][68] V[128][68] P[128][132] redm[512] reds[512]
// ---------------------------------------------------------------------------
#define AQ_STR 68
#define AP_STR 132
#define A_KOFF (128 * AQ_STR)
#define A_VOFF (2 * 128 * AQ_STR)
#define A_POFF (3 * 128 * AQ_STR)
#define A_RMOFF (A_POFF + 128 * AP_STR)
#define A_RSOFF (A_RMOFF + 512)
#define A_SMEM_BYTES ((A_RSOFF + 512) * 4)   // 176128

__global__ void __launch_bounds__(256) attn_kernel()
{
    extern __shared__ u32 sm[];
    u32* Qs = sm;
    u32* Ks = sm + A_KOFF;
    u32* Vs = sm + A_VOFF;
    u32* Ps = sm + A_POFF;
    float* redm = (float*)(sm + A_RMOFF);
    float* reds = (float*)(sm + A_RSOFF);

    const int tid = threadIdx.x;
    const int lane = tid & 31, wid = tid >> 5;
    const int gid = lane >> 2, tidg = lane & 3;
    const int wm1 = wid >> 2, wn1 = wid & 3;   // MMA1: 2m x 4n (64q x 32key)
    const int wm2 = wid >> 1, wn2 = wid & 1;   // MMA2: 4m x 2n (32q x 32d)
    const int qt = blockIdx.x, h = blockIdx.y, b = blockIdx.z;

    const size_t bh = (size_t)(b * HH + h) * NN * DD;
    const float* qg = g_q + bh + (size_t)qt * 128 * DD;
    const float* kg = g_k + bh;
    const float* vg = g_v + bh;

    // stage Q (scale folded)
    #pragma unroll
    for (int i = 0; i < 8; i++) {
        int idx = tid + i * 256;
        int r = idx >> 4, c4 = (idx & 15) << 2;
        float4 v = *(const float4*)&qg[r * 64 + c4];
        u32* p = &Qs[r * AQ_STR + c4];
        p[0] = f2tf(v.x * 0.125f); p[1] = f2tf(v.y * 0.125f);
        p[2] = f2tf(v.z * 0.125f); p[3] = f2tf(v.w * 0.125f);
    }

    float o[2][4][4] = {};

    #pragma unroll 1
    for (int kc = 0; kc < NKC; kc++) {
        __syncthreads();   // Q staged (kc=0); prior MMA2 reads of Vs/Ps done (kc>0)

        const float* kgc = kg + (size_t)kc * 128 * 64;
        const float* vgc = vg + (size_t)kc * 128 * 64;
        #pragma unroll
        for (int i = 0; i < 8; i++) {
            int idx = tid + i * 256;
            int r = idx >> 4, c4 = (idx & 15) << 2;
            float4 kv = *(const float4*)&kgc[r * 64 + c4];
            float4 vv = *(const float4*)&vgc[r * 64 + c4];
            u32* pk = &Ks[r * AQ_STR + c4];
            pk[0] = f2tf(kv.x); pk[1] = f2tf(kv.y); pk[2] = f2tf(kv.z); pk[3] = f2tf(kv.w);
            u32* pv = &Vs[r * AQ_STR + c4];
            pv[0] = f2tf(vv.x); pv[1] = f2tf(vv.y); pv[2] = f2tf(vv.z); pv[3] = f2tf(vv.w);
        }
        __syncthreads();

        // ---- MMA1: S = Q K^T (warp: 64q x 32key, k over D=64) ----
        float s[4][4][4] = {};
        #pragma unroll
        for (int ks = 0; ks < 8; ks++) {
            const int k0 = ks * 8;
            u32 af[4][4], bf[4][2];
            #pragma unroll
            for (int mt = 0; mt < 4; mt++) {
                int r = wm1 * 64 + mt * 16 + gid;
                af[mt][0] = Qs[r * AQ_STR + k0 + tidg];
                af[mt][1] = Qs[(r + 8) * AQ_STR + k0 + tidg];
                af[mt][2] = Qs[r * AQ_STR + k0 + tidg + 4];
                af[mt][3] = Qs[(r + 8) * AQ_STR + k0 + tidg + 4];
            }
            #pragma unroll
            for (int nt = 0; nt < 4; nt++) {
                int c = wn1 * 32 + nt * 8 + gid;
                bf[nt][0] = Ks[c * AQ_STR + k0 + tidg];
                bf[nt][1] = Ks[c * AQ_STR + k0 + tidg + 4];
            }
            #pragma unroll
            for (int mt = 0; mt < 4; mt++)
                #pragma unroll
                for (int nt = 0; nt < 4; nt++)
                    mma8(s[mt][nt], af[mt], bf[nt]);
        }

        // ---- per-row softmax over 128 keys ----
        // thread rows: wm1*64 + mt*16 + h2*8 + gid; cols: wn1*32 + nt*8 + tidg*2 (+1)
        #pragma unroll
        for (int mt = 0; mt < 4; mt++)
            #pragma unroll
            for (int h2 = 0; h2 < 2; h2++) {
                float m = -1e30f;
                #pragma unroll
                for (int nt = 0; nt < 4; nt++) {
                    m = fmaxf(m, s[mt][nt][2 * h2]);
                    m = fmaxf(m, s[mt][nt][2 * h2 + 1]);
                }
                m = fmaxf(m, __shfl_xor_sync(0xffffffffu, m, 1));
                m = fmaxf(m, __shfl_xor_sync(0xffffffffu, m, 2));
                if (tidg == 0) redm[wn1 * 128 + wm1 * 64 + mt * 16 + h2 * 8 + gid] = m;
            }
        __syncthreads();
        #pragma unroll
        for (int mt = 0; mt < 4; mt++)
            #pragma unroll
            for (int h2 = 0; h2 < 2; h2++) {
                int row = wm1 * 64 + mt * 16 + h2 * 8 + gid;
                float m = fmaxf(fmaxf(redm[row], redm[128 + row]),
                                fmaxf(redm[256 + row], redm[384 + row]));
                float sum = 0.f;
                #pragma unroll
                for (int nt = 0; nt < 4; nt++) {
                    float e0 = __expf(s[mt][nt][2 * h2]     - m);
                    float e1 = __expf(s[mt][nt][2 * h2 + 1] - m);
                    s[mt][nt][2 * h2] = e0; s[mt][nt][2 * h2 + 1] = e1;
                    sum += e0 + e1;
                }
                sum += __shfl_xor_sync(0xffffffffu, sum, 1);
                sum += __shfl_xor_sync(0xffffffffu, sum, 2);
                if (tidg == 0) reds[wn1 * 128 + row] = sum;
            }
        __syncthreads();
        #pragma unroll
        for (int mt = 0; mt < 4; mt++)
            #pragma unroll
            for (int h2 = 0; h2 < 2; h2++) {
                int row = wm1 * 64 + mt * 16 + h2 * 8 + gid;
                float inv = 1.0f / (reds[row] + reds[128 + row] + reds[256 + row] + reds[384 + row]);
                #pragma unroll
                for (int nt = 0; nt < 4; nt++) {
                    int col = wn1 * 32 + nt * 8 + tidg * 2;
                    uint2 pv = make_uint2(f2tf(s[mt][nt][2 * h2] * inv),
                                          f2tf(s[mt][nt][2 * h2 + 1] * inv));
                    *(uint2*)&Ps[row * AP_STR + col] = pv;
                }
            }
        __syncthreads();

        // ---- MMA2: O += P V (warp: 32q x 32d, k over 128 keys) ----
        #pragma unroll
        for (int ks = 0; ks < 16; ks++) {
            const int k0 = ks * 8;
            u32 af[2][4], bf[4][2];
            #pragma unroll
            for (int mt = 0; mt < 2; mt++) {
                int r = wm2 * 32 + mt * 16 + gid;
                af[mt][0] = Ps[r * AP_STR + k0 + tidg];
                af[mt][1] = Ps[(r + 8) * AP_STR + k0 + tidg];
                af[mt][2] = Ps[r * AP_STR + k0 + tidg + 4];
                af[mt][3] = Ps[(r + 8) * AP_STR + k0 + tidg + 4];
            }
            #pragma unroll
            for (int nt = 0; nt < 4; nt++) {
                int c = wn2 * 32 + nt * 8 + gid;
                bf[nt][0] = Vs[(k0 + tidg) * AQ_STR + c];
                bf[nt][1] = Vs[(k0 + tidg + 4) * AQ_STR + c];
            }
            #pragma unroll
            for (int mt = 0; mt < 2; mt++)
                #pragma unroll
                for (int nt = 0; nt < 4; nt++)
                    mma8(o[mt][nt], af[mt], bf[nt]);
        }
    }

    // epilogue: O rows = wm2*32 + mt*16 + h2*8 + gid, cols d = wn2*32 + nt*8 + tidg*2
    #pragma unroll
    for (int mt = 0; mt < 2; mt++)
        #pragma unroll
        for (int h2 = 0; h2 < 2; h2++) {
            int n = qt * 128 + wm2 * 32 + mt * 16 + h2 * 8 + gid;
            float* p = &g_a[((size_t)b * NN + n) * CC + h * 64];
            #pragma unroll
            for (int nt = 0; nt < 4; nt++) {
                int d0 = wn2 * 32 + nt * 8 + tidg * 2;
                float2 v = h2 ? make_float2(o[mt][nt][2], o[mt][nt][3])
                              : make_float2(o[mt][nt][0], o[mt][nt][1]);
                *(float2*)&p[d0] = v;
            }
        }
}

// ---------------------------------------------------------------------------
extern "C" void kernel_launch(void* const* d_in, const int* in_sizes, int n_in,
                              void* d_out, int out_size)
{
    const float* x  = (const float*)d_in[0];
    const float* Wq = (const float*)d_in[1];
    const float* Wk = (const float*)d_in[2];
    const float* Wv = (const float*)d_in[3];
    const float* Wp = (const float*)d_in[4];
    const float* bp = (const float*)d_in[5];
    float* out = (float*)d_out;

    cudaFuncSetAttribute(qkv_kernel,  cudaFuncAttributeMaxDynamicSharedMemorySize, G_SMEM_BYTES);
    cudaFuncSetAttribute(proj_kernel, cudaFuncAttributeMaxDynamicSharedMemorySize, G_SMEM_BYTES);
    cudaFuncSetAttribute(attn_kernel, cudaFuncAttributeMaxDynamicSharedMemorySize, A_SMEM_BYTES);

    qkv_kernel<<<dim3(32, 8, 3), 256, G_SMEM_BYTES>>>(x, Wq, Wk, Wv);
    attn_kernel<<<dim3(16, 16, 2), 256, A_SMEM_BYTES>>>();
    proj_kernel<<<dim3(32, 8), 256, G_SMEM_BYTES>>>(Wp, bp, out);
}